// round 4
// baseline (speedup 1.0000x reference)
#include <cuda_runtime.h>
#include <math.h>

#define NPOS 32768      // 32^3 fine positions
#define CIN 64
#define COFF 81         // 3 * 27 offset channels
#define COUT 32

// Scratch (no allocs allowed -> __device__ globals)
__device__ float g_off[COFF * NPOS];            // offset conv output, [ch][pos]
__device__ float g_weff[8 * CIN * COFF * 8];    // parity-combined weights [par][c][o][j]
__device__ float g_wT[27 * CIN * COUT];         // main weights transposed [tap][c][oc]
__device__ float g_scale[COUT];
__device__ float g_shift[COUT];

// ---------------------------------------------------------------------------
// K0: transpose main conv weights to [tap][c][oc] (one-time, tiny).
// ---------------------------------------------------------------------------
__global__ void k_wT(const float* __restrict__ wmain) {
    int t = blockIdx.x * blockDim.x + threadIdx.x;
    if (t >= 27 * CIN * COUT) return;
    int oc  = t & 31;
    int c   = (t >> 5) & 63;
    int tap = t >> 11;
    g_wT[t] = wmain[(oc * CIN + c) * 27 + tap];
}

// ---------------------------------------------------------------------------
// K1: parity-combined effective weights for the offset conv (2x nearest
// upsample + 3^3 conv == per-parity 8-tap conv on the coarse grid).
// ---------------------------------------------------------------------------
__global__ void k_weff(const float* __restrict__ w_off) {
    int t = blockIdx.x * blockDim.x + threadIdx.x;
    if (t >= 8 * CIN * COFF * 8) return;
    int j  = t & 7;
    int o  = (t >> 3) % COFF;
    int c  = (t / (8 * COFF)) % CIN;
    int par = t / (8 * COFF * CIN);
    int pd = (par >> 2) & 1, ph = (par >> 1) & 1, pw = par & 1;
    int jd = (j >> 2) & 1,  jh = (j >> 1) & 1,  jw = j & 1;
    int sd = jd * (1 + pd), nd = (pd != jd) ? 2 : 1;
    int sh = jh * (1 + ph), nh = (ph != jh) ? 2 : 1;
    int sw = jw * (1 + pw), nw = (pw != jw) ? 2 : 1;
    const float* wb = w_off + (o * CIN + c) * 27;
    float s = 0.f;
    for (int a = 0; a < nd; a++)
        for (int bq = 0; bq < nh; bq++)
            for (int cc = 0; cc < nw; cc++)
                s += wb[(sd + a) * 9 + (sh + bq) * 3 + (sw + cc)];
    g_weff[t] = s;   // layout [par][c][o][j]
}

// ---------------------------------------------------------------------------
// K2: offset conv, 3-way split over output channels for occupancy.
// grid = 8 parities x 32 tiles x 3 oc-sections, 128 threads.
// Weights read directly from g_weff with uniform __ldg (broadcast).
// ---------------------------------------------------------------------------
__global__ void __launch_bounds__(128) k_offconv(const float* __restrict__ x,
                                                 const float* __restrict__ b_off) {
    int bid  = blockIdx.x;
    int par  = bid / 96;
    int rest = bid % 96;
    int tile = rest / 3;
    int osec = rest % 3;                      // 27 output channels each
    int q = tile * 128 + threadIdx.x;         // coarse linear index, 0..4095
    int qw = q & 15, qh = (q >> 4) & 15, qd = q >> 8;
    int pd = (par >> 2) & 1, ph = (par >> 1) & 1, pw = par & 1;

    const float* pj[8]; float msk[8];
    #pragma unroll
    for (int j = 0; j < 8; j++) {
        int cd = qd + pd - 1 + ((j >> 2) & 1);
        int ch = qh + ph - 1 + ((j >> 1) & 1);
        int cw = qw + pw - 1 + (j & 1);
        bool v = (unsigned)cd < 16u && (unsigned)ch < 16u && (unsigned)cw < 16u;
        pj[j]  = x + (v ? ((cd * 16 + ch) * 16 + cw) : 0);
        msk[j] = v ? 1.f : 0.f;
    }

    float acc[27];
    #pragma unroll
    for (int o = 0; o < 27; o++) acc[o] = 0.f;

    #pragma unroll 2
    for (int c = 0; c < CIN; c++) {
        float xv[8];
        #pragma unroll
        for (int j = 0; j < 8; j++) xv[j] = msk[j] * __ldg(pj[j] + c * 4096);
        const float4* wr = (const float4*)(g_weff +
            ((size_t)(par * CIN + c) * COFF + osec * 27) * 8);
        #pragma unroll
        for (int o = 0; o < 27; o++) {
            float4 wa = __ldg(wr + o * 2);
            float4 wb2 = __ldg(wr + o * 2 + 1);
            acc[o] += xv[0]*wa.x + xv[1]*wa.y + xv[2]*wa.z + xv[3]*wa.w
                    + xv[4]*wb2.x + xv[5]*wb2.y + xv[6]*wb2.z + xv[7]*wb2.w;
        }
    }
    int df = 2*qd + pd, hf = 2*qh + ph, wf = 2*qw + pw;
    int p = (df * 32 + hf) * 32 + wf;
    #pragma unroll
    for (int o = 0; o < 27; o++)
        g_off[(osec * 27 + o) * NPOS + p] = acc[o] + b_off[osec * 27 + o];
}

// ---------------------------------------------------------------------------
// K3: deformable sampling + per-tap GEMM-let, 4-way channel split.
// No smem weight staging: uniform __ldg from g_wT (broadcast, L1-hot).
// Gather pointers hoisted per tap; channel indexed by immediate offset.
// ---------------------------------------------------------------------------
__global__ void __launch_bounds__(256, 2) k_deform(const float* __restrict__ x,
                                                   const float* __restrict__ bmain,
                                                   float* __restrict__ out) {
    __shared__ float red[2 * 64 * 33];        // reduction, padded vs bank conflicts
    int tid  = threadIdx.x;
    int posi = tid & 63;
    int cs   = tid >> 6;                      // channel quarter 0..3
    int p = blockIdx.x * 64 + posi;
    int wf = p & 31, hf = (p >> 5) & 31, df = p >> 10;

    float acc[COUT];
    #pragma unroll
    for (int i = 0; i < COUT; i++) acc[i] = 0.f;

    const float* xbase = x + cs * 16 * 4096;

    #pragma unroll 1
    for (int tap = 0; tap < 27; tap++) {
        int kd = tap / 9, kh = (tap / 3) % 3, kw = tap % 3;
        float pdc = (float)(df + kd - 1) + __ldg(&g_off[(tap * 3 + 0) * NPOS + p]);
        float phc = (float)(hf + kh - 1) + __ldg(&g_off[(tap * 3 + 1) * NPOS + p]);
        float pwc = (float)(wf + kw - 1) + __ldg(&g_off[(tap * 3 + 2) * NPOS + p]);
        float fd0 = floorf(pdc), fh0 = floorf(phc), fw0 = floorf(pwc);
        int id0 = (int)fd0, ih0 = (int)fh0, iw0 = (int)fw0;
        float fd = pdc - fd0, fh = phc - fh0, fw = pwc - fw0;

        const float* pj[8]; float wts[8];
        #pragma unroll
        for (int j = 0; j < 8; j++) {
            int fid = id0 + ((j >> 2) & 1);
            int fih = ih0 + ((j >> 1) & 1);
            int fiw = iw0 + (j & 1);
            bool v = (unsigned)fid < 32u && (unsigned)fih < 32u && (unsigned)fiw < 32u;
            int cd = fid >> 1, ch = fih >> 1, cw = fiw >> 1;
            pj[j] = xbase + (v ? ((cd * 16 + ch) * 16 + cw) : 0);
            float wd = ((j >> 2) & 1) ? fd : 1.f - fd;
            float wh = ((j >> 1) & 1) ? fh : 1.f - fh;
            float ww = (j & 1) ? fw : 1.f - fw;
            wts[j] = v ? wd * wh * ww : 0.f;
        }

        const float4* wbase = (const float4*)(g_wT + tap * (CIN * COUT)) + cs * 16 * 8;
        #pragma unroll 4
        for (int cc = 0; cc < 16; cc++) {
            float v = 0.f;
            #pragma unroll
            for (int j = 0; j < 8; j++) v += wts[j] * __ldg(pj[j] + cc * 4096);
            const float4* wr = wbase + cc * 8;
            #pragma unroll
            for (int k = 0; k < 8; k++) {
                float4 wv = __ldg(wr + k);
                acc[k*4+0] += v * wv.x;
                acc[k*4+1] += v * wv.y;
                acc[k*4+2] += v * wv.z;
                acc[k*4+3] += v * wv.w;
            }
        }
    }

    // tree-reduce across the 4 channel quarters
    __syncthreads();
    if (cs >= 2) {
        float* dst = red + ((cs - 2) * 64 + posi) * 33;
        #pragma unroll
        for (int oc = 0; oc < COUT; oc++) dst[oc] = acc[oc];
    }
    __syncthreads();
    if (cs < 2) {
        const float* src = red + (cs * 64 + posi) * 33;
        #pragma unroll
        for (int oc = 0; oc < COUT; oc++) acc[oc] += src[oc];
    }
    __syncthreads();
    if (cs == 1) {
        float* dst = red + posi * 33;
        #pragma unroll
        for (int oc = 0; oc < COUT; oc++) dst[oc] = acc[oc];
    }
    __syncthreads();
    if (cs == 0) {
        const float* src = red + posi * 33;
        #pragma unroll
        for (int oc = 0; oc < COUT; oc++)
            out[oc * NPOS + p] = acc[oc] + src[oc] + bmain[oc];
    }
}

// ---------------------------------------------------------------------------
// K4a: per-channel mean/var -> scale/shift (1024-thread blocks).
// K4b: normalize + ReLU in place.
// ---------------------------------------------------------------------------
__global__ void __launch_bounds__(1024) k_bnstat(const float* __restrict__ out,
                                                 const float* __restrict__ gamma,
                                                 const float* __restrict__ beta) {
    __shared__ float ssum[1024], ssq[1024];
    int ch = blockIdx.x;
    const float* base = out + ch * NPOS;
    float s = 0.f, sq = 0.f;
    for (int i = threadIdx.x; i < NPOS; i += 1024) {
        float v = base[i];
        s += v; sq += v * v;
    }
    ssum[threadIdx.x] = s; ssq[threadIdx.x] = sq;
    __syncthreads();
    for (int st = 512; st > 0; st >>= 1) {
        if (threadIdx.x < st) {
            ssum[threadIdx.x] += ssum[threadIdx.x + st];
            ssq[threadIdx.x]  += ssq[threadIdx.x + st];
        }
        __syncthreads();
    }
    if (threadIdx.x == 0) {
        float mean = ssum[0] * (1.f / (float)NPOS);
        float var  = ssq[0] * (1.f / (float)NPOS) - mean * mean;
        float inv  = rsqrtf(var + 1e-5f);
        float a = gamma[ch] * inv;
        g_scale[ch] = a;
        g_shift[ch] = beta[ch] - mean * a;
    }
}

__global__ void k_bnapply(float* __restrict__ out) {
    int idx = blockIdx.x * 256 + threadIdx.x;
    int ch = idx >> 15;
    float v = out[idx] * g_scale[ch] + g_shift[ch];
    out[idx] = fmaxf(v, 0.f);
}

extern "C" void kernel_launch(void* const* d_in, const int* in_sizes, int n_in,
                              void* d_out, int out_size) {
    const float* x     = (const float*)d_in[0];   // (1,64,16,16,16)
    const float* w_off = (const float*)d_in[1];   // (81,64,3,3,3)
    const float* b_off = (const float*)d_in[2];   // (81,)
    const float* w     = (const float*)d_in[3];   // (32,64,3,3,3)
    const float* b     = (const float*)d_in[4];   // (32,)
    const float* gamma = (const float*)d_in[5];   // (32,)
    const float* beta  = (const float*)d_in[6];   // (32,)
    float* out = (float*)d_out;                   // (1,32,32,32,32)

    k_wT<<<(27 * CIN * COUT + 255) / 256, 256>>>(w);
    k_weff<<<(8 * CIN * COFF * 8) / 256, 256>>>(w_off);
    k_offconv<<<768, 128>>>(x, b_off);
    k_deform<<<512, 256>>>(x, b, out);
    k_bnstat<<<COUT, 1024>>>(out, gamma, beta);
    k_bnapply<<<4096, 256>>>(out);
}

// round 5
// speedup vs baseline: 1.3048x; 1.3048x over previous
#include <cuda_runtime.h>
#include <math.h>

#define NPOS 32768      // 32^3 fine positions
#define CIN 64
#define COFF 81         // 3 * 27 offset channels
#define COUT 32

// Scratch (no allocs allowed -> __device__ globals)
__device__ float g_off[COFF * NPOS];            // offset conv output, [ch][pos]
__device__ float g_weff[8 * CIN * COFF * 8];    // parity-combined weights [par][c][o][j]
__device__ float g_wT[27 * CIN * COUT];         // main weights transposed [tap][c][oc]
__device__ float g_scale[COUT];
__device__ float g_shift[COUT];

// ---------------------------------------------------------------------------
// K0: transpose main conv weights to [tap][c][oc] (one-time, tiny).
// ---------------------------------------------------------------------------
__global__ void k_wT(const float* __restrict__ wmain) {
    int t = blockIdx.x * blockDim.x + threadIdx.x;
    if (t >= 27 * CIN * COUT) return;
    int oc  = t & 31;
    int c   = (t >> 5) & 63;
    int tap = t >> 11;
    g_wT[t] = wmain[(oc * CIN + c) * 27 + tap];
}

// ---------------------------------------------------------------------------
// K1: parity-combined effective weights for the offset conv (2x nearest
// upsample + 3^3 conv == per-parity 8-tap conv on the coarse grid).
// ---------------------------------------------------------------------------
__global__ void k_weff(const float* __restrict__ w_off) {
    int t = blockIdx.x * blockDim.x + threadIdx.x;
    if (t >= 8 * CIN * COFF * 8) return;
    int j  = t & 7;
    int o  = (t >> 3) % COFF;
    int c  = (t / (8 * COFF)) % CIN;
    int par = t / (8 * COFF * CIN);
    int pd = (par >> 2) & 1, ph = (par >> 1) & 1, pw = par & 1;
    int jd = (j >> 2) & 1,  jh = (j >> 1) & 1,  jw = j & 1;
    int sd = jd * (1 + pd), nd = (pd != jd) ? 2 : 1;
    int sh = jh * (1 + ph), nh = (ph != jh) ? 2 : 1;
    int sw = jw * (1 + pw), nw = (pw != jw) ? 2 : 1;
    const float* wb = w_off + (o * CIN + c) * 27;
    float s = 0.f;
    for (int a = 0; a < nd; a++)
        for (int bq = 0; bq < nh; bq++)
            for (int cc = 0; cc < nw; cc++)
                s += wb[(sd + a) * 9 + (sh + bq) * 3 + (sw + cc)];
    g_weff[t] = s;   // layout [par][c][o][j]
}

// ---------------------------------------------------------------------------
// K2: offset conv, 2-way channel split for occupancy.
// grid = 8 parities x 64 tiles (512 blocks), 128 threads = 64 pos x 2 halves.
// Weights staged in smem 8 channels at a time; smem reduce of acc[81].
// ---------------------------------------------------------------------------
#define OCHUNK 8
__global__ void __launch_bounds__(128) k_offconv(const float* __restrict__ x,
                                                 const float* __restrict__ b_off) {
    __shared__ float smem_u[2 * OCHUNK * COFF * 8];   // 41.5 KB; reused as red
    float* red = smem_u;                              // 64 * 81 floats (20.7 KB)

    int par  = blockIdx.x >> 6;
    int tile = blockIdx.x & 63;
    int tid  = threadIdx.x;
    int posi = tid & 63;
    int half = tid >> 6;                      // channel half 0/1 (32 ch each)
    int q = tile * 64 + posi;                 // coarse linear index, 0..4095
    int qw = q & 15, qh = (q >> 4) & 15, qd = q >> 8;
    int pd = (par >> 2) & 1, ph = (par >> 1) & 1, pw = par & 1;

    const float* pj[8]; float msk[8];
    #pragma unroll
    for (int j = 0; j < 8; j++) {
        int cd = qd + pd - 1 + ((j >> 2) & 1);
        int ch = qh + ph - 1 + ((j >> 1) & 1);
        int cw = qw + pw - 1 + (j & 1);
        bool v = (unsigned)cd < 16u && (unsigned)ch < 16u && (unsigned)cw < 16u;
        pj[j]  = x + (half * 32 * 4096) + (v ? ((cd * 16 + ch) * 16 + cw) : 0);
        msk[j] = v ? 1.f : 0.f;
    }

    float acc[COFF];
    #pragma unroll
    for (int o = 0; o < COFF; o++) acc[o] = 0.f;

    const int CHUNK_F = OCHUNK * COFF * 8;    // 5184 floats per half-chunk

    #pragma unroll 1
    for (int k = 0; k < 32 / OCHUNK; k++) {
        __syncthreads();
        // stage both halves' chunks (each contiguous in g_weff)
        for (int i = tid; i < 2 * CHUNK_F; i += 128) {
            int h = (i < CHUNK_F) ? 0 : 1;
            int ii = i - h * CHUNK_F;
            smem_u[i] = g_weff[((size_t)(par * CIN + h * 32 + k * OCHUNK) * COFF) * 8 + ii];
        }
        __syncthreads();
        #pragma unroll 1
        for (int cc = 0; cc < OCHUNK; cc++) {
            int cofs = (k * OCHUNK + cc) * 4096;
            float xv[8];
            #pragma unroll
            for (int j = 0; j < 8; j++) xv[j] = msk[j] * __ldg(pj[j] + cofs);
            const float4* wrow = (const float4*)(smem_u + half * CHUNK_F + cc * COFF * 8);
            #pragma unroll
            for (int o = 0; o < COFF; o++) {
                float4 wa = wrow[o * 2];
                float4 wb2 = wrow[o * 2 + 1];
                acc[o] += xv[0]*wa.x + xv[1]*wa.y + xv[2]*wa.z + xv[3]*wa.w
                        + xv[4]*wb2.x + xv[5]*wb2.y + xv[6]*wb2.z + xv[7]*wb2.w;
            }
        }
    }

    // reduce the two halves (stride 81 is odd -> conflict-free)
    __syncthreads();
    if (half == 1) {
        #pragma unroll
        for (int o = 0; o < COFF; o++) red[posi * COFF + o] = acc[o];
    }
    __syncthreads();
    if (half == 0) {
        int df = 2*qd + pd, hf = 2*qh + ph, wf = 2*qw + pw;
        int p = (df * 32 + hf) * 32 + wf;
        #pragma unroll 1
        for (int o = 0; o < COFF; o++)
            g_off[o * NPOS + p] = acc[o] + red[posi * COFF + o] + b_off[o];
    }
}

// ---------------------------------------------------------------------------
// K3: deformable sampling + per-tap GEMM-let, 4-way channel split.
// smem weight staging (LDS broadcast) + pointer-hoisted gathers with
// immediate channel offsets (low ALU). Tree-reduce across 4 quarters.
// ---------------------------------------------------------------------------
__global__ void __launch_bounds__(256, 2) k_deform(const float* __restrict__ x,
                                                   const float* __restrict__ bmain,
                                                   float* __restrict__ out) {
    __shared__ float ws[CIN * COUT];          // per-tap weights [c][oc], 8 KB
    __shared__ float red[2 * 64 * 33];        // reduction, padded vs bank conflicts
    int tid  = threadIdx.x;
    int posi = tid & 63;
    int cs   = tid >> 6;                      // channel quarter 0..3
    int p = blockIdx.x * 64 + posi;
    int wf = p & 31, hf = (p >> 5) & 31, df = p >> 10;

    float acc[COUT];
    #pragma unroll
    for (int i = 0; i < COUT; i++) acc[i] = 0.f;

    const float* xbase = x + cs * 16 * 4096;

    #pragma unroll 1
    for (int tap = 0; tap < 27; tap++) {
        __syncthreads();
        {   // coalesced 8KB copy: g_wT[tap] is contiguous [c][oc]
            const float4* src = (const float4*)(g_wT + tap * CIN * COUT);
            float4* dst = (float4*)ws;
            for (int i = tid; i < CIN * COUT / 4; i += 256) dst[i] = src[i];
        }
        __syncthreads();

        int kd = tap / 9, kh = (tap / 3) % 3, kw = tap % 3;
        float pdc = (float)(df + kd - 1) + __ldg(&g_off[(tap * 3 + 0) * NPOS + p]);
        float phc = (float)(hf + kh - 1) + __ldg(&g_off[(tap * 3 + 1) * NPOS + p]);
        float pwc = (float)(wf + kw - 1) + __ldg(&g_off[(tap * 3 + 2) * NPOS + p]);
        float fd0 = floorf(pdc), fh0 = floorf(phc), fw0 = floorf(pwc);
        int id0 = (int)fd0, ih0 = (int)fh0, iw0 = (int)fw0;
        float fd = pdc - fd0, fh = phc - fh0, fw = pwc - fw0;

        const float* pj[8]; float wts[8];
        #pragma unroll
        for (int j = 0; j < 8; j++) {
            int fid = id0 + ((j >> 2) & 1);
            int fih = ih0 + ((j >> 1) & 1);
            int fiw = iw0 + (j & 1);
            bool v = (unsigned)fid < 32u && (unsigned)fih < 32u && (unsigned)fiw < 32u;
            int cd = fid >> 1, ch = fih >> 1, cw = fiw >> 1;
            pj[j] = xbase + (v ? ((cd * 16 + ch) * 16 + cw) : 0);
            float wd = ((j >> 2) & 1) ? fd : 1.f - fd;
            float wh = ((j >> 1) & 1) ? fh : 1.f - fh;
            float ww = (j & 1) ? fw : 1.f - fw;
            wts[j] = v ? wd * wh * ww : 0.f;
        }

        #pragma unroll 4
        for (int cc = 0; cc < 16; cc++) {
            float v = 0.f;
            #pragma unroll
            for (int j = 0; j < 8; j++) v += wts[j] * __ldg(pj[j] + cc * 4096);
            const float4* wrow = (const float4*)(ws + (cs * 16 + cc) * 32);
            #pragma unroll
            for (int k = 0; k < 8; k++) {
                float4 wv = wrow[k];
                acc[k*4+0] += v * wv.x;
                acc[k*4+1] += v * wv.y;
                acc[k*4+2] += v * wv.z;
                acc[k*4+3] += v * wv.w;
            }
        }
    }

    // tree-reduce across the 4 channel quarters
    __syncthreads();
    if (cs >= 2) {
        float* dst = red + ((cs - 2) * 64 + posi) * 33;
        #pragma unroll
        for (int oc = 0; oc < COUT; oc++) dst[oc] = acc[oc];
    }
    __syncthreads();
    if (cs < 2) {
        const float* src = red + (cs * 64 + posi) * 33;
        #pragma unroll
        for (int oc = 0; oc < COUT; oc++) acc[oc] += src[oc];
    }
    __syncthreads();
    if (cs == 1) {
        float* dst = red + posi * 33;
        #pragma unroll
        for (int oc = 0; oc < COUT; oc++) dst[oc] = acc[oc];
    }
    __syncthreads();
    if (cs == 0) {
        const float* src = red + posi * 33;
        #pragma unroll
        for (int oc = 0; oc < COUT; oc++)
            out[oc * NPOS + p] = acc[oc] + src[oc] + bmain[oc];
    }
}

// ---------------------------------------------------------------------------
// K4a: per-channel mean/var -> scale/shift (1024-thread blocks).
// K4b: normalize + ReLU in place.
// ---------------------------------------------------------------------------
__global__ void __launch_bounds__(1024) k_bnstat(const float* __restrict__ out,
                                                 const float* __restrict__ gamma,
                                                 const float* __restrict__ beta) {
    __shared__ float ssum[1024], ssq[1024];
    int ch = blockIdx.x;
    const float* base = out + ch * NPOS;
    float s = 0.f, sq = 0.f;
    for (int i = threadIdx.x; i < NPOS; i += 1024) {
        float v = base[i];
        s += v; sq += v * v;
    }
    ssum[threadIdx.x] = s; ssq[threadIdx.x] = sq;
    __syncthreads();
    for (int st = 512; st > 0; st >>= 1) {
        if (threadIdx.x < st) {
            ssum[threadIdx.x] += ssum[threadIdx.x + st];
            ssq[threadIdx.x]  += ssq[threadIdx.x + st];
        }
        __syncthreads();
    }
    if (threadIdx.x == 0) {
        float mean = ssum[0] * (1.f / (float)NPOS);
        float var  = ssq[0] * (1.f / (float)NPOS) - mean * mean;
        float inv  = rsqrtf(var + 1e-5f);
        float a = gamma[ch] * inv;
        g_scale[ch] = a;
        g_shift[ch] = beta[ch] - mean * a;
    }
}

__global__ void k_bnapply(float* __restrict__ out) {
    int idx = blockIdx.x * 256 + threadIdx.x;
    int ch = idx >> 15;
    float v = out[idx] * g_scale[ch] + g_shift[ch];
    out[idx] = fmaxf(v, 0.f);
}

extern "C" void kernel_launch(void* const* d_in, const int* in_sizes, int n_in,
                              void* d_out, int out_size) {
    const float* x     = (const float*)d_in[0];   // (1,64,16,16,16)
    const float* w_off = (const float*)d_in[1];   // (81,64,3,3,3)
    const float* b_off = (const float*)d_in[2];   // (81,)
    const float* w     = (const float*)d_in[3];   // (32,64,3,3,3)
    const float* b     = (const float*)d_in[4];   // (32,)
    const float* gamma = (const float*)d_in[5];   // (32,)
    const float* beta  = (const float*)d_in[6];   // (32,)
    float* out = (float*)d_out;                   // (1,32,32,32,32)

    k_wT<<<(27 * CIN * COUT + 255) / 256, 256>>>(w);
    k_weff<<<(8 * CIN * COFF * 8) / 256, 256>>>(w_off);
    k_offconv<<<512, 128>>>(x, b_off);
    k_deform<<<512, 256>>>(x, b, out);
    k_bnstat<<<COUT, 1024>>>(out, gamma, beta);
    k_bnapply<<<4096, 256>>>(out);
}